// round 5
// baseline (speedup 1.0000x reference)
#include <cuda_runtime.h>
#include <cuda_bf16.h>
#include <cstdint>

// ---------------------------------------------------------------------------
// Problem constants
// ---------------------------------------------------------------------------
#define NB    128
#define NQ    36
#define NN    36
#define IND   1024
#define NKER  8
#define OUTK  128
#define OUTD  1024
#define BQ    (NB * NQ)          // 4608
#define MT    36                 // M row-tiles of 128
#define CHUNKS 32                // K chunks of 32 over IND=1024
#define TILE_B 8192              // one tile: 128 rows x 32 bf16 x 2B

#define NPREP 256                // prep tasks (32 chunks x 8 kernels)
#define GRP   136                // per-mt group: 128 agg + 8 gemm
#define NTASK (NPREP + MT * GRP) // 5152
#define NPERS 296                // persistent blocks (~2 per SM)

typedef unsigned long long ull;

// ---------------------------------------------------------------------------
// Device-global scratch + dependency counters
// ---------------------------------------------------------------------------
__device__ __align__(128) __nv_bfloat16 g_a_hi[(size_t)NKER * MT * CHUNKS * (TILE_B / 2)];
__device__ __align__(128) __nv_bfloat16 g_a_lo[(size_t)NKER * MT * CHUNKS * (TILE_B / 2)];
__device__ __align__(128) __nv_bfloat16 g_b_hi[(size_t)NKER * CHUNKS * (TILE_B / 2)];
__device__ __align__(128) __nv_bfloat16 g_b_lo[(size_t)NKER * CHUNKS * (TILE_B / 2)];

__device__ int g_cnt_agg[MT];
__device__ int g_cnt_prep;
__device__ int g_next;

// ---------------------------------------------------------------------------
// PTX helpers (non-"a" features only: valid on plain sm_103 target)
// ---------------------------------------------------------------------------
__device__ __forceinline__ void fma2(ull& d, ull a, ull b) {
    asm("fma.rn.f32x2 %0, %1, %2, %0;" : "+l"(d) : "l"(a), "l"(b));
}
__device__ __forceinline__ ull pack2(float x) {
    ull r;
    asm("mov.b64 %0, {%1, %1};" : "=l"(r) : "r"(__float_as_uint(x)));
    return r;
}
__device__ __forceinline__ uint32_t smem_u32(const void* p) {
    uint32_t a;
    asm("{ .reg .u64 t; cvta.to.shared.u64 t, %1; cvt.u32.u64 %0, t; }" : "=r"(a) : "l"(p));
    return a;
}
__device__ __forceinline__ void cp16(uint32_t d, const void* s) {
    asm volatile("cp.async.cg.shared.global [%0], [%1], 16;" :: "r"(d), "l"(s));
}
__device__ __forceinline__ void ldx4(uint32_t* r, uint32_t addr) {
    asm volatile("ldmatrix.sync.aligned.m8n8.x4.shared.b16 {%0,%1,%2,%3}, [%4];"
                 : "=r"(r[0]), "=r"(r[1]), "=r"(r[2]), "=r"(r[3]) : "r"(addr));
}
__device__ __forceinline__ void mma16816(float* d, const uint32_t* a, const uint32_t* b) {
    asm volatile(
        "mma.sync.aligned.m16n8k16.row.col.f32.bf16.bf16.f32 "
        "{%0,%1,%2,%3}, {%4,%5,%6,%7}, {%8,%9}, {%0,%1,%2,%3};"
        : "+f"(d[0]), "+f"(d[1]), "+f"(d[2]), "+f"(d[3])
        : "r"(a[0]), "r"(a[1]), "r"(a[2]), "r"(a[3]), "r"(b[0]), "r"(b[1]));
}
__device__ __forceinline__ int ld_acq(const int* p) {
    int v;
    asm volatile("ld.acquire.gpu.global.b32 %0, [%1];" : "=r"(v) : "l"(p) : "memory");
    return v;
}

// ---------------------------------------------------------------------------
// Reset counters (runs first each replay)
// ---------------------------------------------------------------------------
__global__ void k_reset()
{
    if (threadIdx.x < MT) g_cnt_agg[threadIdx.x] = 0;
    if (threadIdx.x == MT) g_cnt_prep = 0;
    if (threadIdx.x == MT + 1) g_next = 0;
}

// ---------------------------------------------------------------------------
// Role: conv_w prep. One (kc,kk) tile per task.
// ---------------------------------------------------------------------------
__device__ void role_prep(int rb, char* dsm, const float* __restrict__ convw)
{
    const int kc  = rb & 31;
    const int kk  = rb >> 5;
    const int tid = threadIdx.x;

    float* s = reinterpret_cast<float*>(dsm);
    const float4* src = reinterpret_cast<const float4*>(
        convw + (size_t)kk * (IND * OUTK) + (size_t)kc * (32 * OUTK));
    float4* sd = reinterpret_cast<float4*>(s);
#pragma unroll
    for (int i = 0; i < 4; i++)
        sd[tid + i * 256] = __ldg(&src[tid + i * 256]);
    __syncthreads();

    if (tid < 128) {
        const size_t tbase = ((size_t)kk * CHUNKS + kc) * TILE_B;
        const int n = tid;
        const int swz = (n >> 1) & 3;
#pragma unroll
        for (int g = 0; g < 4; g++) {
            union { __nv_bfloat16 h[8]; uint4 u; } H, L;
#pragma unroll
            for (int j = 0; j < 8; j++) {
                const float v = s[(g * 8 + j) * 128 + n];
                const __nv_bfloat16 h = __float2bfloat16_rn(v);
                H.h[j] = h;
                L.h[j] = __float2bfloat16_rn(v - __bfloat162float(h));
            }
            const uint32_t sw = (uint32_t)(n * 64 + 16 * (g ^ swz));
            *reinterpret_cast<uint4*>((char*)g_b_hi + tbase + sw) = H.u;
            *reinterpret_cast<uint4*>((char*)g_b_lo + tbase + sw) = L.u;
        }
    }
    __syncthreads();
    if (tid == 0) {
        __threadfence();
        atomicAdd(&g_cnt_prep, 1);
    }
}

// ---------------------------------------------------------------------------
// Role: gaussian weights + aggregation for one (b,q). 256 threads.
// ---------------------------------------------------------------------------
__device__ void role_agg(int bq, char* dsm,
    const float* __restrict__ feats, const float* __restrict__ coords,
    const float* __restrict__ mrho,  const float* __restrict__ mtheta,
    const float* __restrict__ prho,  const float* __restrict__ ptheta)
{
    ull* w2s = reinterpret_cast<ull*>(dsm);   // [NN][NKER]
    const int tid = threadIdx.x;

    if (tid < NN) {
        const float rho = coords[((size_t)bq * NN + tid) * 2 + 0];
        const float th  = coords[((size_t)bq * NN + tid) * 2 + 1];
        float w[NKER];
        float s = 0.0f;
        const float TWO_PI = 6.283185307179586f;
#pragma unroll
        for (int k = 0; k < NKER; k++) {
            const float dr = rho - __ldg(&mrho[k]);
            const float pr = __ldg(&prho[k]);
            const float wr = expf(-0.5f * dr * dr / (1e-14f + pr * pr));
            const float fa = fabsf(th - __ldg(&mtheta[k]));
            const float sa = fabsf(TWO_PI - fa);
            const float an = fminf(fa, sa);
            const float pt = __ldg(&ptheta[k]);
            const float wt = expf(-0.5f * an * an / (1e-14f + pt * pt));
            float wv = wr * wt;
            wv = isnan(wv) ? 0.0f : wv;
            w[k] = wv;
            s += wv;
        }
#pragma unroll
        for (int k = 0; k < NKER; k++)
            w2s[tid * NKER + k] = pack2(w[k] / s);
    }
    __syncthreads();

    ull acc[NKER][2];
#pragma unroll
    for (int k = 0; k < NKER; k++) { acc[k][0] = 0ULL; acc[k][1] = 0ULL; }

    const ulonglong2* p = reinterpret_cast<const ulonglong2*>(feats)
                        + (size_t)bq * (NN * IND / 4) + tid;

#pragma unroll 4
    for (int n = 0; n < NN; n++) {
        const ulonglong2 f = __ldcs(p);
        p += IND / 4;
#pragma unroll
        for (int k = 0; k < NKER; k++) {
            const ull wk = w2s[n * NKER + k];
            fma2(acc[k][0], f.x, wk);
            fma2(acc[k][1], f.y, wk);
        }
    }

    const int row   = bq & 127;
    const int mt128 = bq >> 7;
    const int kc    = tid >> 3;
    const int g     = (tid >> 1) & 3;
    const int half  = tid & 1;
    const uint32_t sw = (uint32_t)(row * 64 + 16 * (g ^ ((row >> 1) & 3)) + 8 * half);

#pragma unroll
    for (int k = 0; k < NKER; k++) {
        float x0 = __uint_as_float((uint32_t)acc[k][0]);
        float x1 = __uint_as_float((uint32_t)(acc[k][0] >> 32));
        float x2 = __uint_as_float((uint32_t)acc[k][1]);
        float x3 = __uint_as_float((uint32_t)(acc[k][1] >> 32));

        __nv_bfloat16 h0 = __float2bfloat16_rn(x0);
        __nv_bfloat16 h1 = __float2bfloat16_rn(x1);
        __nv_bfloat16 h2 = __float2bfloat16_rn(x2);
        __nv_bfloat16 h3 = __float2bfloat16_rn(x3);
        __nv_bfloat16 l0 = __float2bfloat16_rn(x0 - __bfloat162float(h0));
        __nv_bfloat16 l1 = __float2bfloat16_rn(x1 - __bfloat162float(h1));
        __nv_bfloat16 l2 = __float2bfloat16_rn(x2 - __bfloat162float(h2));
        __nv_bfloat16 l3 = __float2bfloat16_rn(x3 - __bfloat162float(h3));

        union { __nv_bfloat16 h[4]; ull u; } H, L;
        H.h[0] = h0; H.h[1] = h1; H.h[2] = h2; H.h[3] = h3;
        L.h[0] = l0; L.h[1] = l1; L.h[2] = l2; L.h[3] = l3;

        const size_t tile = ((size_t)(k * MT + mt128) * CHUNKS + kc) * TILE_B;
        *reinterpret_cast<ull*>((char*)g_a_hi + tile + sw) = H.u;
        *reinterpret_cast<ull*>((char*)g_a_lo + tile + sw) = L.u;
    }

    __syncthreads();
    if (tid == 0) {
        __threadfence();
        atomicAdd(&g_cnt_agg[mt128], 1);
    }
}

// ---------------------------------------------------------------------------
// Role: HMMA GEMM (bf16x3 split). Tile 128x128, 8 warps, 3-stage cp.async.
// ---------------------------------------------------------------------------
#define NST 3
#define STAGE_B 32768   // Ah 8K | Al 8K | Bh 8K | Bl 8K

__device__ void role_gemm(int mt, int kk, char* dsm, float* __restrict__ out)
{
    const int tid  = threadIdx.x;
    const int wid  = tid >> 5;
    const int lane = tid & 31;

    // dependencies: all prep tiles + all 128 agg rows of this mt.
    // Task ordering guarantees these were already pulled by running blocks.
    if (tid == 0) {
        while (ld_acq(&g_cnt_prep) < NPREP) __nanosleep(128);
        while (ld_acq(&g_cnt_agg[mt]) < 128) __nanosleep(128);
    }
    __syncthreads();

    const uint32_t sbase = smem_u32(dsm);

    const int wm = (wid >> 2) * 64;
    const int wn = (wid & 3) * 32;

    const char* Abh = (const char*)g_a_hi + (size_t)(kk * MT + mt) * CHUNKS * TILE_B;
    const char* Abl = (const char*)g_a_lo + (size_t)(kk * MT + mt) * CHUNKS * TILE_B;
    const char* Bbh = (const char*)g_b_hi + (size_t)kk * CHUNKS * TILE_B;
    const char* Bbl = (const char*)g_b_lo + (size_t)kk * CHUNKS * TILE_B;

    const int j  = lane >> 3;
    const int rr = lane & 7;
    const int a_row  = wm + ((j & 1) << 3) + rr;
    const int a_gsel = j >> 1;
    const int swzA   = (a_row >> 1) & 3;
    const int b_n    = wn + ((j >> 1) << 3) + rr;
    const int b_gsel = j & 1;
    const int swzB   = (b_n >> 1) & 3;

    float acc[4][4][4];
#pragma unroll
    for (int i = 0; i < 4; i++)
#pragma unroll
        for (int t = 0; t < 4; t++)
#pragma unroll
            for (int r = 0; r < 4; r++) acc[i][t][r] = 0.0f;

    auto load_chunk = [&](int c, uint32_t sb) {
        const uint32_t o = (uint32_t)(tid * 16);
        const char* ah = Abh + (size_t)c * TILE_B + o;
        const char* al = Abl + (size_t)c * TILE_B + o;
        const char* bh = Bbh + (size_t)c * TILE_B + o;
        const char* bl = Bbl + (size_t)c * TILE_B + o;
        cp16(sb + o,         ah);
        cp16(sb + 4096 + o,  ah + 4096);
        cp16(sb + 8192 + o,  al);
        cp16(sb + 12288 + o, al + 4096);
        cp16(sb + 16384 + o, bh);
        cp16(sb + 20480 + o, bh + 4096);
        cp16(sb + 24576 + o, bl);
        cp16(sb + 28672 + o, bl + 4096);
        asm volatile("cp.async.commit_group;");
    };

    load_chunk(0, sbase);
    load_chunk(1, sbase + STAGE_B);

    for (int c = 0; c < CHUNKS; c++) {
        if (c < CHUNKS - 1) {
            asm volatile("cp.async.wait_group %0;" :: "n"(1));
        } else {
            asm volatile("cp.async.wait_group %0;" :: "n"(0));
        }
        __syncthreads();
        if (c + 2 < CHUNKS)
            load_chunk(c + 2, sbase + (uint32_t)((c + 2) % NST) * STAGE_B);

        const uint32_t sb  = sbase + (uint32_t)(c % NST) * STAGE_B;
        const uint32_t ahb = sb;
        const uint32_t alb = sb + 8192;
        const uint32_t bhb = sb + 16384;
        const uint32_t blb = sb + 24576;

#pragma unroll
        for (int s = 0; s < 2; s++) {
            uint32_t bh[8], bl[8];
#pragma unroll
            for (int p = 0; p < 2; p++) {
                const uint32_t boff = (uint32_t)((b_n + 16 * p) * 64
                                    + 16 * ((2 * s + b_gsel) ^ swzB));
                ldx4(&bh[4 * p], bhb + boff);
                ldx4(&bl[4 * p], blb + boff);
            }
#pragma unroll
            for (int i = 0; i < 4; i++) {
                uint32_t ah[4], al[4];
                const uint32_t aoff = (uint32_t)((a_row + 16 * i) * 64
                                    + 16 * ((2 * s + a_gsel) ^ swzA));
                ldx4(ah, ahb + aoff);
                ldx4(al, alb + aoff);
#pragma unroll
                for (int t = 0; t < 4; t++) {
                    mma16816(acc[i][t], ah, &bh[2 * t]);
                    mma16816(acc[i][t], ah, &bl[2 * t]);
                    mma16816(acc[i][t], al, &bh[2 * t]);
                }
            }
        }
    }

#pragma unroll
    for (int i = 0; i < 4; i++) {
        const int r0 = mt * 128 + wm + 16 * i + (lane >> 2);
#pragma unroll
        for (int t = 0; t < 4; t++) {
            const int cN = kk * OUTK + wn + 8 * t + 2 * (lane & 3);
            float2 v0; v0.x = acc[i][t][0]; v0.y = acc[i][t][1];
            float2 v1; v1.x = acc[i][t][2]; v1.y = acc[i][t][3];
            *reinterpret_cast<float2*>(out + (size_t)r0 * OUTD + cN)       = v0;
            *reinterpret_cast<float2*>(out + (size_t)(r0 + 8) * OUTD + cN) = v1;
        }
    }
}

// ---------------------------------------------------------------------------
// Persistent work-queue kernel. Task order:
//   [0,256):               prep tiles
//   then per mt in 0..35:  128 agg rows, then 8 gemm (kk) tasks
// Tasks are pulled via atomicAdd in order -> any dependency of a pulled task
// was already pulled by an executing block -> deadlock-free; gemm (tensor-
// bound) overlaps with agg (DRAM-bound) of later mts.
// ---------------------------------------------------------------------------
__global__ void __launch_bounds__(256, 2) k_persist(
    const float* __restrict__ feats, const float* __restrict__ coords,
    const float* __restrict__ mrho,  const float* __restrict__ mtheta,
    const float* __restrict__ prho,  const float* __restrict__ ptheta,
    const float* __restrict__ convw, float* __restrict__ out)
{
    extern __shared__ char dsm[];
    __shared__ int s_task;

    for (;;) {
        if (threadIdx.x == 0) s_task = atomicAdd(&g_next, 1);
        __syncthreads();
        const int t = s_task;
        if (t >= NTASK) return;

        if (t < NPREP) {
            role_prep(t, dsm, convw);
        } else {
            const int u  = t - NPREP;
            const int g  = u / GRP;
            const int r  = u % GRP;
            if (r < 128) {
                role_agg(g * 128 + r, dsm, feats, coords, mrho, mtheta, prho, ptheta);
            } else {
                role_gemm(g, r - 128, dsm, out);
            }
        }
        __syncthreads();
    }
}

// ---------------------------------------------------------------------------
extern "C" void kernel_launch(void* const* d_in, const int* in_sizes, int n_in,
                              void* d_out, int out_size)
{
    const float* feats  = (const float*)d_in[0];
    const float* coords = (const float*)d_in[1];
    const float* mrho   = (const float*)d_in[2];
    const float* mtheta = (const float*)d_in[3];
    const float* prho   = (const float*)d_in[4];
    const float* ptheta = (const float*)d_in[5];
    const float* convw  = (const float*)d_in[6];
    float* out = (float*)d_out;

    cudaFuncSetAttribute(k_persist, cudaFuncAttributeMaxDynamicSharedMemorySize,
                         NST * STAGE_B);

    k_reset<<<1, 64>>>();
    k_persist<<<NPERS, 256, NST * STAGE_B>>>(feats, coords, mrho, mtheta,
                                             prho, ptheta, convw, out);
}

// round 6
// speedup vs baseline: 1.4848x; 1.4848x over previous
#include <cuda_runtime.h>
#include <cuda_bf16.h>
#include <cstdint>

// ---------------------------------------------------------------------------
// Problem constants
// ---------------------------------------------------------------------------
#define NB    128
#define NQ    36
#define NN    36
#define IND   1024
#define NKER  8
#define OUTK  128
#define OUTD  1024
#define BQ    (NB * NQ)          // 4608
#define MT    36                 // M row-tiles of 128
#define CHUNKS 32                // K chunks of 32 over IND=1024
#define TILE_B 8192              // one tile: 128 rows x 32 bf16 x 2B

typedef unsigned long long ull;

// ---------------------------------------------------------------------------
// Device-global scratch. A (agg) and B (conv_w^T) stored as bf16 hi/lo in a
// pre-swizzled tile format: tile = 128 rows x 32 cols bf16, rows of 64B,
// 16B groups XOR-swizzled by ((row>>1)&3) -> conflict-free ldmatrix.
// Each (chunk) tile is 8KB CONTIGUOUS -> single cp.async.bulk per tile.
// A layout: [kker][mt(36)][chunk(32)] x tile;  B: [kker][chunk(32)] x tile.
// ---------------------------------------------------------------------------
__device__ __align__(128) __nv_bfloat16 g_a_hi[(size_t)NKER * MT * CHUNKS * (TILE_B / 2)];
__device__ __align__(128) __nv_bfloat16 g_a_lo[(size_t)NKER * MT * CHUNKS * (TILE_B / 2)];
__device__ __align__(128) __nv_bfloat16 g_b_hi[(size_t)NKER * CHUNKS * (TILE_B / 2)];
__device__ __align__(128) __nv_bfloat16 g_b_lo[(size_t)NKER * CHUNKS * (TILE_B / 2)];

// ---------------------------------------------------------------------------
// PTX helpers (non-"a" features only: valid on plain sm_103 target)
// ---------------------------------------------------------------------------
__device__ __forceinline__ void fma2(ull& d, ull a, ull b) {
    asm("fma.rn.f32x2 %0, %1, %2, %0;" : "+l"(d) : "l"(a), "l"(b));
}
__device__ __forceinline__ ull pack2(float x) {
    ull r;
    asm("mov.b64 %0, {%1, %1};" : "=l"(r) : "r"(__float_as_uint(x)));
    return r;
}
__device__ __forceinline__ uint32_t smem_u32(const void* p) {
    uint32_t a;
    asm("{ .reg .u64 t; cvta.to.shared.u64 t, %1; cvt.u32.u64 %0, t; }" : "=r"(a) : "l"(p));
    return a;
}
__device__ __forceinline__ void ldx4(uint32_t* r, uint32_t addr) {
    asm volatile("ldmatrix.sync.aligned.m8n8.x4.shared.b16 {%0,%1,%2,%3}, [%4];"
                 : "=r"(r[0]), "=r"(r[1]), "=r"(r[2]), "=r"(r[3]) : "r"(addr));
}
__device__ __forceinline__ void mma16816(float* d, const uint32_t* a, const uint32_t* b) {
    asm volatile(
        "mma.sync.aligned.m16n8k16.row.col.f32.bf16.bf16.f32 "
        "{%0,%1,%2,%3}, {%4,%5,%6,%7}, {%8,%9}, {%0,%1,%2,%3};"
        : "+f"(d[0]), "+f"(d[1]), "+f"(d[2]), "+f"(d[3])
        : "r"(a[0]), "r"(a[1]), "r"(a[2]), "r"(a[3]), "r"(b[0]), "r"(b[1]));
}
__device__ __forceinline__ void mbar_init(uint32_t addr, uint32_t cnt) {
    asm volatile("mbarrier.init.shared.b64 [%0], %1;" :: "r"(addr), "r"(cnt) : "memory");
}
__device__ __forceinline__ void mbar_expect_tx(uint32_t addr, uint32_t bytes) {
    asm volatile("mbarrier.arrive.expect_tx.shared.b64 _, [%0], %1;"
                 :: "r"(addr), "r"(bytes) : "memory");
}
__device__ __forceinline__ void mbar_wait_acq(uint32_t addr, uint32_t parity) {
    asm volatile(
        "{\n\t.reg .pred P;\n\t"
        "W%=:\n\t"
        "mbarrier.try_wait.parity.acquire.cta.shared::cta.b64 P, [%0], %1;\n\t"
        "@!P bra W%=;\n\t}"
        :: "r"(addr), "r"(parity) : "memory");
}
__device__ __forceinline__ void bulk_g2s(uint32_t dst, const void* src, uint32_t bytes,
                                         uint32_t mbar) {
    asm volatile(
        "cp.async.bulk.shared::cta.global.mbarrier::complete_tx::bytes [%0], [%1], %2, [%3];"
        :: "r"(dst), "l"(src), "r"(bytes), "r"(mbar) : "memory");
}

// ---------------------------------------------------------------------------
// Kernel 1: gaussian weights + weighted aggregation over neighbourhood.
// One block per (b,q), 256 threads, thread owns 4 consecutive d-cols for all
// 8 kernels. Emits bf16 hi/lo directly in the swizzled GEMM tile layout.
// ---------------------------------------------------------------------------
__global__ void __launch_bounds__(256) k_agg(
    const float* __restrict__ feats, const float* __restrict__ coords,
    const float* __restrict__ mrho,  const float* __restrict__ mtheta,
    const float* __restrict__ prho,  const float* __restrict__ ptheta)
{
    __shared__ ull w2s[NN][NKER];

    const int bq  = blockIdx.x;
    const int tid = threadIdx.x;

    if (tid < NN) {
        const float rho = coords[((size_t)bq * NN + tid) * 2 + 0];
        const float th  = coords[((size_t)bq * NN + tid) * 2 + 1];
        float w[NKER];
        float s = 0.0f;
        const float TWO_PI = 6.283185307179586f;
#pragma unroll
        for (int k = 0; k < NKER; k++) {
            const float dr = rho - __ldg(&mrho[k]);
            const float pr = __ldg(&prho[k]);
            const float wr = expf(-0.5f * dr * dr / (1e-14f + pr * pr));
            const float fa = fabsf(th - __ldg(&mtheta[k]));
            const float sa = fabsf(TWO_PI - fa);
            const float an = fminf(fa, sa);
            const float pt = __ldg(&ptheta[k]);
            const float wt = expf(-0.5f * an * an / (1e-14f + pt * pt));
            float wv = wr * wt;
            wv = isnan(wv) ? 0.0f : wv;
            w[k] = wv;
            s += wv;
        }
#pragma unroll
        for (int k = 0; k < NKER; k++)
            w2s[tid][k] = pack2(w[k] / s);
    }
    __syncthreads();

    ull acc[NKER][2];
#pragma unroll
    for (int k = 0; k < NKER; k++) { acc[k][0] = 0ULL; acc[k][1] = 0ULL; }

    const ulonglong2* p = reinterpret_cast<const ulonglong2*>(feats)
                        + (size_t)bq * (NN * IND / 4) + tid;

#pragma unroll 4
    for (int n = 0; n < NN; n++) {
        const ulonglong2 f = __ldcs(p);
        p += IND / 4;
#pragma unroll
        for (int k = 0; k < NKER; k++) {
            const ull wk = w2s[n][k];
            fma2(acc[k][0], f.x, wk);
            fma2(acc[k][1], f.y, wk);
        }
    }

    // store bf16 hi/lo into swizzled tile layout
    const int row   = bq & 127;
    const int mt128 = bq >> 7;
    const int kc    = tid >> 3;          // chunk index 0..31
    const int g     = (tid >> 1) & 3;    // 16B group within 64B row
    const int half  = tid & 1;           // low/high 8B of group
    const uint32_t sw = (uint32_t)(row * 64 + 16 * (g ^ ((row >> 1) & 3)) + 8 * half);

#pragma unroll
    for (int k = 0; k < NKER; k++) {
        float x0 = __uint_as_float((uint32_t)acc[k][0]);
        float x1 = __uint_as_float((uint32_t)(acc[k][0] >> 32));
        float x2 = __uint_as_float((uint32_t)acc[k][1]);
        float x3 = __uint_as_float((uint32_t)(acc[k][1] >> 32));

        __nv_bfloat16 h0 = __float2bfloat16_rn(x0);
        __nv_bfloat16 h1 = __float2bfloat16_rn(x1);
        __nv_bfloat16 h2 = __float2bfloat16_rn(x2);
        __nv_bfloat16 h3 = __float2bfloat16_rn(x3);
        __nv_bfloat16 l0 = __float2bfloat16_rn(x0 - __bfloat162float(h0));
        __nv_bfloat16 l1 = __float2bfloat16_rn(x1 - __bfloat162float(h1));
        __nv_bfloat16 l2 = __float2bfloat16_rn(x2 - __bfloat162float(h2));
        __nv_bfloat16 l3 = __float2bfloat16_rn(x3 - __bfloat162float(h3));

        union { __nv_bfloat16 h[4]; ull u; } H, L;
        H.h[0] = h0; H.h[1] = h1; H.h[2] = h2; H.h[3] = h3;
        L.h[0] = l0; L.h[1] = l1; L.h[2] = l2; L.h[3] = l3;

        const size_t tile = ((size_t)(k * MT + mt128) * CHUNKS + kc) * TILE_B;
        *reinterpret_cast<ull*>((char*)g_a_hi + tile + sw) = H.u;
        *reinterpret_cast<ull*>((char*)g_a_lo + tile + sw) = L.u;
    }
}

// ---------------------------------------------------------------------------
// Kernel 2: conv_w (k,d,o) -> B^T tiles [kker][chunk] of 128 n-rows x 32 k.
// ---------------------------------------------------------------------------
__global__ void __launch_bounds__(128) k_prep(const float* __restrict__ convw)
{
    __shared__ float s[32 * 128];
    const int kc = blockIdx.x;     // 0..31
    const int kk = blockIdx.y;     // 0..7
    const int tid = threadIdx.x;   // 0..127

    const float4* src = reinterpret_cast<const float4*>(
        convw + (size_t)kk * (IND * OUTK) + (size_t)kc * (32 * OUTK));
    float4* sd = reinterpret_cast<float4*>(s);
#pragma unroll
    for (int i = 0; i < 8; i++)
        sd[tid + i * 128] = __ldg(&src[tid + i * 128]);
    __syncthreads();

    const size_t tbase = ((size_t)kk * CHUNKS + kc) * TILE_B;
    const int n = tid;
    const int swz = (n >> 1) & 3;
#pragma unroll
    for (int g = 0; g < 4; g++) {
        union { __nv_bfloat16 h[8]; uint4 u; } H, L;
#pragma unroll
        for (int j = 0; j < 8; j++) {
            const float v = s[(g * 8 + j) * 128 + n];
            const __nv_bfloat16 h = __float2bfloat16_rn(v);
            H.h[j] = h;
            L.h[j] = __float2bfloat16_rn(v - __bfloat162float(h));
        }
        const uint32_t sw = (uint32_t)(n * 64 + 16 * (g ^ swz));
        *reinterpret_cast<uint4*>((char*)g_b_hi + tbase + sw) = H.u;
        *reinterpret_cast<uint4*>((char*)g_b_lo + tbase + sw) = L.u;
    }
}

// ---------------------------------------------------------------------------
// Kernel 3: HMMA GEMM, bf16x3 split (hi*hi + hi*lo + lo*hi).
// Block 128x128, 8 warps (warp tile 64x32), 3-stage pipeline fed by
// cp.async.bulk (one thread issues 4 x 8KB copies per chunk; mbarrier
// complete_tx signals stage ready). LSU is freed for ldmatrix only.
// grid (36, 8), 96KB dynamic smem -> 2 blocks/SM, one wave.
// ---------------------------------------------------------------------------
#define NST 3
#define STAGE_B 32768   // Ah 8K | Al 8K | Bh 8K | Bl 8K

__global__ void __launch_bounds__(256, 2) k_mma(float* __restrict__ out)
{
    extern __shared__ char dsm[];
    __shared__ __align__(8) ull s_mbar[NST];

    const uint32_t sbase = smem_u32(dsm);
    const uint32_t mb    = smem_u32(s_mbar);

    const int tid  = threadIdx.x;
    const int wid  = tid >> 5;
    const int lane = tid & 31;
    const int mt   = blockIdx.x;   // 0..35
    const int kk   = blockIdx.y;   // 0..7

    const int wm = (wid >> 2) * 64;   // warp M offset (0/64)
    const int wn = (wid & 3) * 32;    // warp N offset (0/32/64/96)

    const char* Abh = (const char*)g_a_hi + (size_t)(kk * MT + mt) * CHUNKS * TILE_B;
    const char* Abl = (const char*)g_a_lo + (size_t)(kk * MT + mt) * CHUNKS * TILE_B;
    const char* Bbh = (const char*)g_b_hi + (size_t)kk * CHUNKS * TILE_B;
    const char* Bbl = (const char*)g_b_lo + (size_t)kk * CHUNKS * TILE_B;

    // one bulk fill: 4 x 8KB contiguous tiles into stage s for chunk c
    auto issue_chunk = [&](int c, int s) {
        const uint32_t sb = sbase + (uint32_t)s * STAGE_B;
        const uint32_t fb = mb + 8u * (uint32_t)s;
        mbar_expect_tx(fb, STAGE_B);
        bulk_g2s(sb + 0,     Abh + (size_t)c * TILE_B, TILE_B, fb);
        bulk_g2s(sb + 8192,  Abl + (size_t)c * TILE_B, TILE_B, fb);
        bulk_g2s(sb + 16384, Bbh + (size_t)c * TILE_B, TILE_B, fb);
        bulk_g2s(sb + 24576, Bbl + (size_t)c * TILE_B, TILE_B, fb);
    };

    if (tid == 0) {
#pragma unroll
        for (int s = 0; s < NST; s++) mbar_init(mb + 8u * s, 1);
    }
    __syncthreads();
    if (tid == 0) {
        issue_chunk(0, 0);
        issue_chunk(1, 1);
    }

    // ldmatrix per-lane address components
    const int j  = lane >> 3;
    const int rr = lane & 7;
    const int a_row  = wm + ((j & 1) << 3) + rr;   // + 16*i
    const int a_gsel = j >> 1;                     // + 2*s
    const int swzA   = (a_row >> 1) & 3;
    const int b_n    = wn + ((j >> 1) << 3) + rr;  // + 16*p
    const int b_gsel = j & 1;                      // + 2*s
    const int swzB   = (b_n >> 1) & 3;

    float acc[4][4][4];
#pragma unroll
    for (int i = 0; i < 4; i++)
#pragma unroll
        for (int t = 0; t < 4; t++)
#pragma unroll
            for (int r = 0; r < 4; r++) acc[i][t][r] = 0.0f;

    int ph[NST] = {0, 0, 0};

    for (int c = 0; c < CHUNKS; c++) {
        const int s = c % NST;
        mbar_wait_acq(mb + 8u * s, ph[s]);
        ph[s] ^= 1;

        const uint32_t sb  = sbase + (uint32_t)s * STAGE_B;
        const uint32_t ahb = sb;
        const uint32_t alb = sb + 8192;
        const uint32_t bhb = sb + 16384;
        const uint32_t blb = sb + 24576;

#pragma unroll
        for (int ss = 0; ss < 2; ss++) {
            uint32_t bh[8], bl[8];
#pragma unroll
            for (int p = 0; p < 2; p++) {
                const uint32_t boff = (uint32_t)((b_n + 16 * p) * 64
                                    + 16 * ((2 * ss + b_gsel) ^ swzB));
                ldx4(&bh[4 * p], bhb + boff);
                ldx4(&bl[4 * p], blb + boff);
            }
#pragma unroll
            for (int i = 0; i < 4; i++) {
                uint32_t ah[4], al[4];
                const uint32_t aoff = (uint32_t)((a_row + 16 * i) * 64
                                    + 16 * ((2 * ss + a_gsel) ^ swzA));
                ldx4(ah, ahb + aoff);
                ldx4(al, alb + aoff);
#pragma unroll
                for (int t = 0; t < 4; t++) {
                    mma16816(acc[i][t], ah, &bh[2 * t]);
                    mma16816(acc[i][t], ah, &bl[2 * t]);
                    mma16816(acc[i][t], al, &bh[2 * t]);
                }
            }
        }

        // all warps finished reading stage s for chunk c -> safe to refill
        // stage (c+2)%NST (its prior occupant was chunk c-1, already consumed)
        __syncthreads();
        if (c + 2 < CHUNKS && tid == 0)
            issue_chunk(c + 2, (c + 2) % NST);
    }

    // epilogue
#pragma unroll
    for (int i = 0; i < 4; i++) {
        const int r0 = mt * 128 + wm + 16 * i + (lane >> 2);
#pragma unroll
        for (int t = 0; t < 4; t++) {
            const int cN = kk * OUTK + wn + 8 * t + 2 * (lane & 3);
            float2 v0; v0.x = acc[i][t][0]; v0.y = acc[i][t][1];
            float2 v1; v1.x = acc[i][t][2]; v1.y = acc[i][t][3];
            *reinterpret_cast<float2*>(out + (size_t)r0 * OUTD + cN)       = v0;
            *reinterpret_cast<float2*>(out + (size_t)(r0 + 8) * OUTD + cN) = v1;
        }
    }
}

// ---------------------------------------------------------------------------
extern "C" void kernel_launch(void* const* d_in, const int* in_sizes, int n_in,
                              void* d_out, int out_size)
{
    const float* feats  = (const float*)d_in[0];
    const float* coords = (const float*)d_in[1];
    const float* mrho   = (const float*)d_in[2];
    const float* mtheta = (const float*)d_in[3];
    const float* prho   = (const float*)d_in[4];
    const float* ptheta = (const float*)d_in[5];
    const float* convw  = (const float*)d_in[6];
    float* out = (float*)d_out;

    cudaFuncSetAttribute(k_mma, cudaFuncAttributeMaxDynamicSharedMemorySize,
                         NST * STAGE_B);

    dim3 gp(CHUNKS, NKER);
    k_prep<<<gp, 128>>>(convw);
    k_agg<<<BQ, 256>>>(feats, coords, mrho, mtheta, prho, ptheta);
    dim3 gg(MT, NKER);
    k_mma<<<gg, 256, NST * STAGE_B>>>(out);
}

// round 7
// speedup vs baseline: 1.6353x; 1.1013x over previous
#include <cuda_runtime.h>
#include <cuda_fp16.h>
#include <cstdint>

// ---------------------------------------------------------------------------
// Problem constants
// ---------------------------------------------------------------------------
#define NB    128
#define NQ    36
#define NN    36
#define IND   1024
#define NKER  8
#define OUTK  128
#define OUTD  1024
#define BQ    (NB * NQ)          // 4608
#define MT    36                 // M row-tiles of 128
#define CHUNKS 32                // K chunks of 32 over IND=1024
#define TILE_B 8192              // one tile: 128 rows x 32 fp16 x 2B

typedef unsigned long long ull;

// ---------------------------------------------------------------------------
// Device-global scratch. A (agg) stored as fp16 hi/lo (exact to 2^-24),
// B (conv_w^T) stored as single fp16 (error 2^-12 -> output rel ~1e-4).
// Tile format: 128 rows x 32 cols fp16, rows of 64B, 16B groups XOR-swizzled
// by ((row>>1)&3) -> conflict-free ldmatrix. Each tile is 8KB contiguous.
// A layout: [kker][mt(36)][chunk(32)] x tile;  B: [kker][chunk(32)] x tile.
// ---------------------------------------------------------------------------
__device__ __align__(128) __half g_a_hi[(size_t)NKER * MT * CHUNKS * (TILE_B / 2)];
__device__ __align__(128) __half g_a_lo[(size_t)NKER * MT * CHUNKS * (TILE_B / 2)];
__device__ __align__(128) __half g_b_hi[(size_t)NKER * CHUNKS * (TILE_B / 2)];

// ---------------------------------------------------------------------------
// PTX helpers (non-"a" features only: valid on plain sm_103 target)
// ---------------------------------------------------------------------------
__device__ __forceinline__ void fma2(ull& d, ull a, ull b) {
    asm("fma.rn.f32x2 %0, %1, %2, %0;" : "+l"(d) : "l"(a), "l"(b));
}
__device__ __forceinline__ ull pack2(float x) {
    ull r;
    asm("mov.b64 %0, {%1, %1};" : "=l"(r) : "r"(__float_as_uint(x)));
    return r;
}
__device__ __forceinline__ uint32_t smem_u32(const void* p) {
    uint32_t a;
    asm("{ .reg .u64 t; cvta.to.shared.u64 t, %1; cvt.u32.u64 %0, t; }" : "=r"(a) : "l"(p));
    return a;
}
__device__ __forceinline__ void ldx4(uint32_t* r, uint32_t addr) {
    asm volatile("ldmatrix.sync.aligned.m8n8.x4.shared.b16 {%0,%1,%2,%3}, [%4];"
                 : "=r"(r[0]), "=r"(r[1]), "=r"(r[2]), "=r"(r[3]) : "r"(addr));
}
__device__ __forceinline__ void mma16816(float* d, const uint32_t* a, const uint32_t* b) {
    asm volatile(
        "mma.sync.aligned.m16n8k16.row.col.f32.f16.f16.f32 "
        "{%0,%1,%2,%3}, {%4,%5,%6,%7}, {%8,%9}, {%0,%1,%2,%3};"
        : "+f"(d[0]), "+f"(d[1]), "+f"(d[2]), "+f"(d[3])
        : "r"(a[0]), "r"(a[1]), "r"(a[2]), "r"(a[3]), "r"(b[0]), "r"(b[1]));
}
__device__ __forceinline__ void mbar_init(uint32_t addr, uint32_t cnt) {
    asm volatile("mbarrier.init.shared.b64 [%0], %1;" :: "r"(addr), "r"(cnt) : "memory");
}
__device__ __forceinline__ void mbar_expect_tx(uint32_t addr, uint32_t bytes) {
    asm volatile("mbarrier.arrive.expect_tx.shared.b64 _, [%0], %1;"
                 :: "r"(addr), "r"(bytes) : "memory");
}
__device__ __forceinline__ void mbar_wait_acq(uint32_t addr, uint32_t parity) {
    asm volatile(
        "{\n\t.reg .pred P;\n\t"
        "W%=:\n\t"
        "mbarrier.try_wait.parity.acquire.cta.shared::cta.b64 P, [%0], %1;\n\t"
        "@!P bra W%=;\n\t}"
        :: "r"(addr), "r"(parity) : "memory");
}
__device__ __forceinline__ void bulk_g2s(uint32_t dst, const void* src, uint32_t bytes,
                                         uint32_t mbar) {
    asm volatile(
        "cp.async.bulk.shared::cta.global.mbarrier::complete_tx::bytes [%0], [%1], %2, [%3];"
        :: "r"(dst), "l"(src), "r"(bytes), "r"(mbar) : "memory");
}

// ---------------------------------------------------------------------------
// Kernel 1: gaussian weights + weighted aggregation over neighbourhood.
// One block per (b,q), 256 threads, thread owns 4 consecutive d-cols for all
// 8 kernels. Emits fp16 hi/lo directly in the swizzled GEMM tile layout.
// launch_bounds(256,4): cap regs at 64 -> 4 blocks/SM -> 4x loads in flight.
// ---------------------------------------------------------------------------
__global__ void __launch_bounds__(256, 4) k_agg(
    const float* __restrict__ feats, const float* __restrict__ coords,
    const float* __restrict__ mrho,  const float* __restrict__ mtheta,
    const float* __restrict__ prho,  const float* __restrict__ ptheta)
{
    __shared__ ull w2s[NN][NKER];

    const int bq  = blockIdx.x;
    const int tid = threadIdx.x;

    if (tid < NN) {
        const float rho = coords[((size_t)bq * NN + tid) * 2 + 0];
        const float th  = coords[((size_t)bq * NN + tid) * 2 + 1];
        float w[NKER];
        float s = 0.0f;
        const float TWO_PI = 6.283185307179586f;
#pragma unroll
        for (int k = 0; k < NKER; k++) {
            const float dr = rho - __ldg(&mrho[k]);
            const float pr = __ldg(&prho[k]);
            const float wr = expf(-0.5f * dr * dr / (1e-14f + pr * pr));
            const float fa = fabsf(th - __ldg(&mtheta[k]));
            const float sa = fabsf(TWO_PI - fa);
            const float an = fminf(fa, sa);
            const float pt = __ldg(&ptheta[k]);
            const float wt = expf(-0.5f * an * an / (1e-14f + pt * pt));
            float wv = wr * wt;
            wv = isnan(wv) ? 0.0f : wv;
            w[k] = wv;
            s += wv;
        }
#pragma unroll
        for (int k = 0; k < NKER; k++)
            w2s[tid][k] = pack2(w[k] / s);
    }
    __syncthreads();

    ull acc[NKER][2];
#pragma unroll
    for (int k = 0; k < NKER; k++) { acc[k][0] = 0ULL; acc[k][1] = 0ULL; }

    const ulonglong2* p = reinterpret_cast<const ulonglong2*>(feats)
                        + (size_t)bq * (NN * IND / 4) + tid;

#pragma unroll 4
    for (int n = 0; n < NN; n++) {
        const ulonglong2 f = __ldcs(p);
        p += IND / 4;
#pragma unroll
        for (int k = 0; k < NKER; k++) {
            const ull wk = w2s[n][k];
            fma2(acc[k][0], f.x, wk);
            fma2(acc[k][1], f.y, wk);
        }
    }

    // store fp16 hi/lo into swizzled tile layout (streaming stores)
    const int row   = bq & 127;
    const int mt128 = bq >> 7;
    const int kc    = tid >> 3;          // chunk index 0..31
    const int g     = (tid >> 1) & 3;    // 16B group within 64B row
    const int half_ = tid & 1;           // low/high 8B of group
    const uint32_t sw = (uint32_t)(row * 64 + 16 * (g ^ ((row >> 1) & 3)) + 8 * half_);

#pragma unroll
    for (int k = 0; k < NKER; k++) {
        float x0 = __uint_as_float((uint32_t)acc[k][0]);
        float x1 = __uint_as_float((uint32_t)(acc[k][0] >> 32));
        float x2 = __uint_as_float((uint32_t)acc[k][1]);
        float x3 = __uint_as_float((uint32_t)(acc[k][1] >> 32));

        __half h0 = __float2half_rn(x0);
        __half h1 = __float2half_rn(x1);
        __half h2 = __float2half_rn(x2);
        __half h3 = __float2half_rn(x3);
        __half l0 = __float2half_rn(x0 - __half2float(h0));
        __half l1 = __float2half_rn(x1 - __half2float(h1));
        __half l2 = __float2half_rn(x2 - __half2float(h2));
        __half l3 = __float2half_rn(x3 - __half2float(h3));

        union { __half h[4]; ull u; } H, L;
        H.h[0] = h0; H.h[1] = h1; H.h[2] = h2; H.h[3] = h3;
        L.h[0] = l0; L.h[1] = l1; L.h[2] = l2; L.h[3] = l3;

        const size_t tile = ((size_t)(k * MT + mt128) * CHUNKS + kc) * TILE_B;
        __stcs(reinterpret_cast<ull*>((char*)g_a_hi + tile + sw), H.u);
        __stcs(reinterpret_cast<ull*>((char*)g_a_lo + tile + sw), L.u);
    }
}

// ---------------------------------------------------------------------------
// Kernel 2: conv_w (k,d,o) -> B^T tiles [kker][chunk] of 128 n-rows x 32 k.
// Single fp16 (hi only).
// ---------------------------------------------------------------------------
__global__ void __launch_bounds__(128) k_prep(const float* __restrict__ convw)
{
    __shared__ float s[32 * 128];
    const int kc = blockIdx.x;     // 0..31
    const int kk = blockIdx.y;     // 0..7
    const int tid = threadIdx.x;   // 0..127

    const float4* src = reinterpret_cast<const float4*>(
        convw + (size_t)kk * (IND * OUTK) + (size_t)kc * (32 * OUTK));
    float4* sd = reinterpret_cast<float4*>(s);
#pragma unroll
    for (int i = 0; i < 8; i++)
        sd[tid + i * 128] = __ldg(&src[tid + i * 128]);
    __syncthreads();

    const size_t tbase = ((size_t)kk * CHUNKS + kc) * TILE_B;
    const int n = tid;
    const int swz = (n >> 1) & 3;
#pragma unroll
    for (int g = 0; g < 4; g++) {
        union { __half h[8]; uint4 u; } H;
#pragma unroll
        for (int j = 0; j < 8; j++)
            H.h[j] = __float2half_rn(s[(g * 8 + j) * 128 + n]);
        const uint32_t sw = (uint32_t)(n * 64 + 16 * (g ^ swz));
        *reinterpret_cast<uint4*>((char*)g_b_hi + tbase + sw) = H.u;
    }
}

// ---------------------------------------------------------------------------
// Kernel 3: HMMA GEMM, fp16x2 split (Ah*Bh + Al*Bh; A exact to 2^-24, B
// truncated to fp16 -> output rel err ~1e-4). Block 128x128, 8 warps (warp
// tile 64x32), 4-stage pipeline fed by cp.async.bulk + mbarrier.
// grid (36, 8), 96KB dynamic smem -> 2 blocks/SM, one wave.
// ---------------------------------------------------------------------------
#define NST 4
#define STAGE_B 24576   // Ah 8K | Al 8K | Bh 8K

__global__ void __launch_bounds__(256, 2) k_mma(float* __restrict__ out)
{
    extern __shared__ char dsm[];
    __shared__ __align__(8) ull s_mbar[NST];

    const uint32_t sbase = smem_u32(dsm);
    const uint32_t mb    = smem_u32(s_mbar);

    const int tid  = threadIdx.x;
    const int wid  = tid >> 5;
    const int lane = tid & 31;
    const int mt   = blockIdx.x;   // 0..35
    const int kk   = blockIdx.y;   // 0..7

    const int wm = (wid >> 2) * 64;   // warp M offset (0/64)
    const int wn = (wid & 3) * 32;    // warp N offset (0/32/64/96)

    const char* Abh = (const char*)g_a_hi + (size_t)(kk * MT + mt) * CHUNKS * TILE_B;
    const char* Abl = (const char*)g_a_lo + (size_t)(kk * MT + mt) * CHUNKS * TILE_B;
    const char* Bbh = (const char*)g_b_hi + (size_t)kk * CHUNKS * TILE_B;

    auto issue_chunk = [&](int c, int s) {
        const uint32_t sb = sbase + (uint32_t)s * STAGE_B;
        const uint32_t fb = mb + 8u * (uint32_t)s;
        mbar_expect_tx(fb, STAGE_B);
        bulk_g2s(sb + 0,     Abh + (size_t)c * TILE_B, TILE_B, fb);
        bulk_g2s(sb + 8192,  Abl + (size_t)c * TILE_B, TILE_B, fb);
        bulk_g2s(sb + 16384, Bbh + (size_t)c * TILE_B, TILE_B, fb);
    };

    if (tid == 0) {
#pragma unroll
        for (int s = 0; s < NST; s++) mbar_init(mb + 8u * s, 1);
    }
    __syncthreads();
    if (tid == 0) {
        issue_chunk(0, 0);
        issue_chunk(1, 1);
        issue_chunk(2, 2);
    }

    // ldmatrix per-lane address components
    const int j  = lane >> 3;
    const int rr = lane & 7;
    const int a_row  = wm + ((j & 1) << 3) + rr;   // + 16*i
    const int a_gsel = j >> 1;                     // + 2*ss
    const int swzA   = (a_row >> 1) & 3;
    const int b_n    = wn + ((j >> 1) << 3) + rr;  // + 16*p
    const int b_gsel = j & 1;                      // + 2*ss
    const int swzB   = (b_n >> 1) & 3;

    float acc[4][4][4];
#pragma unroll
    for (int i = 0; i < 4; i++)
#pragma unroll
        for (int t = 0; t < 4; t++)
#pragma unroll
            for (int r = 0; r < 4; r++) acc[i][t][r] = 0.0f;

    int ph[NST] = {0, 0, 0, 0};

    for (int c = 0; c < CHUNKS; c++) {
        const int s = c % NST;
        mbar_wait_acq(mb + 8u * s, ph[s]);
        ph[s] ^= 1;

        const uint32_t sb  = sbase + (uint32_t)s * STAGE_B;
        const uint32_t ahb = sb;
        const uint32_t alb = sb + 8192;
        const uint32_t bhb = sb + 16384;

#pragma unroll
        for (int ss = 0; ss < 2; ss++) {
            uint32_t bh[8];
#pragma unroll
            for (int p = 0; p < 2; p++) {
                const uint32_t boff = (uint32_t)((b_n + 16 * p) * 64
                                    + 16 * ((2 * ss + b_gsel) ^ swzB));
                ldx4(&bh[4 * p], bhb + boff);
            }
#pragma unroll
            for (int i = 0; i < 4; i++) {
                uint32_t ah[4], al[4];
                const uint32_t aoff = (uint32_t)((a_row + 16 * i) * 64
                                    + 16 * ((2 * ss + a_gsel) ^ swzA));
                ldx4(ah, ahb + aoff);
                ldx4(al, alb + aoff);
#pragma unroll
                for (int t = 0; t < 4; t++) {
                    mma16816(acc[i][t], ah, &bh[2 * t]);
                    mma16816(acc[i][t], al, &bh[2 * t]);
                }
            }
        }

        __syncthreads();
        if (c + 3 < CHUNKS && tid == 0)
            issue_chunk(c + 3, (c + 3) % NST);
    }

    // epilogue
#pragma unroll
    for (int i = 0; i < 4; i++) {
        const int r0 = mt * 128 + wm + 16 * i + (lane >> 2);
#pragma unroll
        for (int t = 0; t < 4; t++) {
            const int cN = kk * OUTK + wn + 8 * t + 2 * (lane & 3);
            float2 v0; v0.x = acc[i][t][0]; v0.y = acc[i][t][1];
            float2 v1; v1.x = acc[i][t][2]; v1.y = acc[i][t][3];
            *reinterpret_cast<float2*>(out + (size_t)r0 * OUTD + cN)       = v0;
            *reinterpret_cast<float2*>(out + (size_t)(r0 + 8) * OUTD + cN) = v1;
        }
    }
}

// ---------------------------------------------------------------------------
extern "C" void kernel_launch(void* const* d_in, const int* in_sizes, int n_in,
                              void* d_out, int out_size)
{
    const float* feats  = (const float*)d_in[0];
    const float* coords = (const float*)d_in[1];
    const float* mrho   = (const float*)d_in[2];
    const float* mtheta = (const float*)d_in[3];
    const float* prho   = (const float*)d_in[4];
    const float* ptheta = (const float*)d_in[5];
    const float* convw  = (const float*)d_in[6];
    float* out = (float*)d_out;

    cudaFuncSetAttribute(k_mma, cudaFuncAttributeMaxDynamicSharedMemorySize,
                         NST * STAGE_B);

    dim3 gp(CHUNKS, NKER);
    k_prep<<<gp, 128>>>(convw);
    k_agg<<<BQ, 256>>>(feats, coords, mrho, mtheta, prho, ptheta);
    dim3 gg(MT, NKER);
    k_mma<<<gg, 256, NST * STAGE_B>>>(out);
}

// round 8
// speedup vs baseline: 1.9097x; 1.1678x over previous
#include <cuda_runtime.h>
#include <cuda_fp16.h>
#include <cstdint>

// ---------------------------------------------------------------------------
// Problem constants
// ---------------------------------------------------------------------------
#define NB    128
#define NQ    36
#define NN    36
#define IND   1024
#define NKER  8
#define OUTK  128
#define OUTD  1024
#define BQ    (NB * NQ)          // 4608
#define MT    36                 // M row-tiles of 128
#define CHUNKS 32                // K chunks of 32 over IND=1024
#define TILE_B 8192              // one tile: 128 rows x 32 fp16 x 2B

typedef unsigned long long ull;

// ---------------------------------------------------------------------------
// Device-global scratch. A (agg) and B (conv_w^T) both single fp16
// (independent roundings -> output rel err ~3e-4, threshold 1e-3).
// Tile format: 128 rows x 32 cols fp16, rows of 64B, 16B groups XOR-swizzled
// by ((row>>1)&3) -> conflict-free ldmatrix. Each tile is 8KB contiguous.
// A layout: [kker][mt(36)][chunk(32)] x tile;  B: [kker][chunk(32)] x tile.
// ---------------------------------------------------------------------------
__device__ __align__(128) __half g_a_hi[(size_t)NKER * MT * CHUNKS * (TILE_B / 2)];
__device__ __align__(128) __half g_b_hi[(size_t)NKER * CHUNKS * (TILE_B / 2)];

// ---------------------------------------------------------------------------
// PTX helpers (non-"a" features only: valid on plain sm_103 target)
// ---------------------------------------------------------------------------
__device__ __forceinline__ void fma2(ull& d, ull a, ull b) {
    asm("fma.rn.f32x2 %0, %1, %2, %0;" : "+l"(d) : "l"(a), "l"(b));
}
__device__ __forceinline__ ull pack2(float x) {
    ull r;
    asm("mov.b64 %0, {%1, %1};" : "=l"(r) : "r"(__float_as_uint(x)));
    return r;
}
__device__ __forceinline__ uint32_t smem_u32(const void* p) {
    uint32_t a;
    asm("{ .reg .u64 t; cvta.to.shared.u64 t, %1; cvt.u32.u64 %0, t; }" : "=r"(a) : "l"(p));
    return a;
}
__device__ __forceinline__ void ldx4(uint32_t* r, uint32_t addr) {
    asm volatile("ldmatrix.sync.aligned.m8n8.x4.shared.b16 {%0,%1,%2,%3}, [%4];"
                 : "=r"(r[0]), "=r"(r[1]), "=r"(r[2]), "=r"(r[3]) : "r"(addr));
}
__device__ __forceinline__ void mma16816(float* d, const uint32_t* a, const uint32_t* b) {
    asm volatile(
        "mma.sync.aligned.m16n8k16.row.col.f32.f16.f16.f32 "
        "{%0,%1,%2,%3}, {%4,%5,%6,%7}, {%8,%9}, {%0,%1,%2,%3};"
        : "+f"(d[0]), "+f"(d[1]), "+f"(d[2]), "+f"(d[3])
        : "r"(a[0]), "r"(a[1]), "r"(a[2]), "r"(a[3]), "r"(b[0]), "r"(b[1]));
}
__device__ __forceinline__ void mbar_init(uint32_t addr, uint32_t cnt) {
    asm volatile("mbarrier.init.shared.b64 [%0], %1;" :: "r"(addr), "r"(cnt) : "memory");
}
__device__ __forceinline__ void mbar_expect_tx(uint32_t addr, uint32_t bytes) {
    asm volatile("mbarrier.arrive.expect_tx.shared.b64 _, [%0], %1;"
                 :: "r"(addr), "r"(bytes) : "memory");
}
__device__ __forceinline__ void mbar_wait_acq(uint32_t addr, uint32_t parity) {
    asm volatile(
        "{\n\t.reg .pred P;\n\t"
        "W%=:\n\t"
        "mbarrier.try_wait.parity.acquire.cta.shared::cta.b64 P, [%0], %1;\n\t"
        "@!P bra W%=;\n\t}"
        :: "r"(addr), "r"(parity) : "memory");
}
__device__ __forceinline__ void bulk_g2s(uint32_t dst, const void* src, uint32_t bytes,
                                         uint32_t mbar) {
    asm volatile(
        "cp.async.bulk.shared::cta.global.mbarrier::complete_tx::bytes [%0], [%1], %2, [%3];"
        :: "r"(dst), "l"(src), "r"(bytes), "r"(mbar) : "memory");
}

// ---------------------------------------------------------------------------
// Kernel 1: gaussian weights + weighted aggregation over neighbourhood.
// One block per (b,q), 256 threads, thread owns 4 consecutive d-cols for all
// 8 kernels. Emits single fp16 directly in the swizzled GEMM tile layout.
// ---------------------------------------------------------------------------
__global__ void __launch_bounds__(256, 4) k_agg(
    const float* __restrict__ feats, const float* __restrict__ coords,
    const float* __restrict__ mrho,  const float* __restrict__ mtheta,
    const float* __restrict__ prho,  const float* __restrict__ ptheta)
{
    __shared__ ull w2s[NN][NKER];

    const int bq  = blockIdx.x;
    const int tid = threadIdx.x;

    if (tid < NN) {
        const float rho = coords[((size_t)bq * NN + tid) * 2 + 0];
        const float th  = coords[((size_t)bq * NN + tid) * 2 + 1];
        float w[NKER];
        float s = 0.0f;
        const float TWO_PI = 6.283185307179586f;
#pragma unroll
        for (int k = 0; k < NKER; k++) {
            const float dr = rho - __ldg(&mrho[k]);
            const float pr = __ldg(&prho[k]);
            const float wr = expf(-0.5f * dr * dr / (1e-14f + pr * pr));
            const float fa = fabsf(th - __ldg(&mtheta[k]));
            const float sa = fabsf(TWO_PI - fa);
            const float an = fminf(fa, sa);
            const float pt = __ldg(&ptheta[k]);
            const float wt = expf(-0.5f * an * an / (1e-14f + pt * pt));
            float wv = wr * wt;
            wv = isnan(wv) ? 0.0f : wv;
            w[k] = wv;
            s += wv;
        }
#pragma unroll
        for (int k = 0; k < NKER; k++)
            w2s[tid][k] = pack2(w[k] / s);
    }
    __syncthreads();

    ull acc[NKER][2];
#pragma unroll
    for (int k = 0; k < NKER; k++) { acc[k][0] = 0ULL; acc[k][1] = 0ULL; }

    const ulonglong2* p = reinterpret_cast<const ulonglong2*>(feats)
                        + (size_t)bq * (NN * IND / 4) + tid;

#pragma unroll 4
    for (int n = 0; n < NN; n++) {
        const ulonglong2 f = __ldcs(p);
        p += IND / 4;
#pragma unroll
        for (int k = 0; k < NKER; k++) {
            const ull wk = w2s[n][k];
            fma2(acc[k][0], f.x, wk);
            fma2(acc[k][1], f.y, wk);
        }
    }

    // store single fp16 into swizzled tile layout (streaming stores)
    const int row   = bq & 127;
    const int mt128 = bq >> 7;
    const int kc    = tid >> 3;          // chunk index 0..31
    const int g     = (tid >> 1) & 3;    // 16B group within 64B row
    const int half_ = tid & 1;           // low/high 8B of group
    const uint32_t sw = (uint32_t)(row * 64 + 16 * (g ^ ((row >> 1) & 3)) + 8 * half_);

#pragma unroll
    for (int k = 0; k < NKER; k++) {
        float x0 = __uint_as_float((uint32_t)acc[k][0]);
        float x1 = __uint_as_float((uint32_t)(acc[k][0] >> 32));
        float x2 = __uint_as_float((uint32_t)acc[k][1]);
        float x3 = __uint_as_float((uint32_t)(acc[k][1] >> 32));

        union { __half h[4]; ull u; } H;
        H.h[0] = __float2half_rn(x0);
        H.h[1] = __float2half_rn(x1);
        H.h[2] = __float2half_rn(x2);
        H.h[3] = __float2half_rn(x3);

        const size_t tile = ((size_t)(k * MT + mt128) * CHUNKS + kc) * TILE_B;
        __stcs(reinterpret_cast<ull*>((char*)g_a_hi + tile + sw), H.u);
    }
}

// ---------------------------------------------------------------------------
// Kernel 2: conv_w (k,d,o) -> B^T tiles [kker][chunk] of 128 n-rows x 32 k.
// ---------------------------------------------------------------------------
__global__ void __launch_bounds__(128) k_prep(const float* __restrict__ convw)
{
    __shared__ float s[32 * 128];
    const int kc = blockIdx.x;     // 0..31
    const int kk = blockIdx.y;     // 0..7
    const int tid = threadIdx.x;   // 0..127

    const float4* src = reinterpret_cast<const float4*>(
        convw + (size_t)kk * (IND * OUTK) + (size_t)kc * (32 * OUTK));
    float4* sd = reinterpret_cast<float4*>(s);
#pragma unroll
    for (int i = 0; i < 8; i++)
        sd[tid + i * 128] = __ldg(&src[tid + i * 128]);
    __syncthreads();

    const size_t tbase = ((size_t)kk * CHUNKS + kc) * TILE_B;
    const int n = tid;
    const int swz = (n >> 1) & 3;
#pragma unroll
    for (int g = 0; g < 4; g++) {
        union { __half h[8]; uint4 u; } H;
#pragma unroll
        for (int j = 0; j < 8; j++)
            H.h[j] = __float2half_rn(s[(g * 8 + j) * 128 + n]);
        const uint32_t sw = (uint32_t)(n * 64 + 16 * (g ^ swz));
        *reinterpret_cast<uint4*>((char*)g_b_hi + tbase + sw) = H.u;
    }
}

// ---------------------------------------------------------------------------
// Kernel 3: HMMA GEMM, single fp16 pass. Block 128x128, 8 warps (warp tile
// 64x32), 6-stage pipeline fed by cp.async.bulk + mbarrier.
// grid (36, 8), 96KB dynamic smem -> 2 blocks/SM, one wave.
// ---------------------------------------------------------------------------
#define NST 6
#define STAGE_B 16384   // Ah 8K | Bh 8K

__global__ void __launch_bounds__(256, 2) k_mma(float* __restrict__ out)
{
    extern __shared__ char dsm[];
    __shared__ __align__(8) ull s_mbar[NST];

    const uint32_t sbase = smem_u32(dsm);
    const uint32_t mb    = smem_u32(s_mbar);

    const int tid  = threadIdx.x;
    const int wid  = tid >> 5;
    const int lane = tid & 31;
    const int mt   = blockIdx.x;   // 0..35
    const int kk   = blockIdx.y;   // 0..7

    const int wm = (wid >> 2) * 64;   // warp M offset (0/64)
    const int wn = (wid & 3) * 32;    // warp N offset (0/32/64/96)

    const char* Abh = (const char*)g_a_hi + (size_t)(kk * MT + mt) * CHUNKS * TILE_B;
    const char* Bbh = (const char*)g_b_hi + (size_t)kk * CHUNKS * TILE_B;

    auto issue_chunk = [&](int c, int s) {
        const uint32_t sb = sbase + (uint32_t)s * STAGE_B;
        const uint32_t fb = mb + 8u * (uint32_t)s;
        mbar_expect_tx(fb, STAGE_B);
        bulk_g2s(sb + 0,    Abh + (size_t)c * TILE_B, TILE_B, fb);
        bulk_g2s(sb + 8192, Bbh + (size_t)c * TILE_B, TILE_B, fb);
    };

    if (tid == 0) {
#pragma unroll
        for (int s = 0; s < NST; s++) mbar_init(mb + 8u * s, 1);
    }
    __syncthreads();
    if (tid == 0) {
#pragma unroll
        for (int s = 0; s < NST - 1; s++) issue_chunk(s, s);
    }

    // ldmatrix per-lane address components
    const int j  = lane >> 3;
    const int rr = lane & 7;
    const int a_row  = wm + ((j & 1) << 3) + rr;   // + 16*i
    const int a_gsel = j >> 1;                     // + 2*ss
    const int swzA   = (a_row >> 1) & 3;
    const int b_n    = wn + ((j >> 1) << 3) + rr;  // + 16*p
    const int b_gsel = j & 1;                      // + 2*ss
    const int swzB   = (b_n >> 1) & 3;

    float acc[4][4][4];
#pragma unroll
    for (int i = 0; i < 4; i++)
#pragma unroll
        for (int t = 0; t < 4; t++)
#pragma unroll
            for (int r = 0; r < 4; r++) acc[i][t][r] = 0.0f;

    int ph[NST] = {0, 0, 0, 0, 0, 0};

    for (int c = 0; c < CHUNKS; c++) {
        const int s = c % NST;
        mbar_wait_acq(mb + 8u * s, ph[s]);
        ph[s] ^= 1;

        const uint32_t sb  = sbase + (uint32_t)s * STAGE_B;
        const uint32_t ahb = sb;
        const uint32_t bhb = sb + 8192;

#pragma unroll
        for (int ss = 0; ss < 2; ss++) {
            uint32_t bh[8];
#pragma unroll
            for (int p = 0; p < 2; p++) {
                const uint32_t boff = (uint32_t)((b_n + 16 * p) * 64
                                    + 16 * ((2 * ss + b_gsel) ^ swzB));
                ldx4(&bh[4 * p], bhb + boff);
            }
#pragma unroll
            for (int i = 0; i < 4; i++) {
                uint32_t ah[4];
                const uint32_t aoff = (uint32_t)((a_row + 16 * i) * 64
                                    + 16 * ((2 * ss + a_gsel) ^ swzA));
                ldx4(ah, ahb + aoff);
#pragma unroll
                for (int t = 0; t < 4; t++)
                    mma16816(acc[i][t], ah, &bh[2 * t]);
            }
        }

        __syncthreads();
        if (c + NST - 1 < CHUNKS && tid == 0)
            issue_chunk(c + NST - 1, (c + NST - 1) % NST);
    }

    // epilogue
#pragma unroll
    for (int i = 0; i < 4; i++) {
        const int r0 = mt * 128 + wm + 16 * i + (lane >> 2);
#pragma unroll
        for (int t = 0; t < 4; t++) {
            const int cN = kk * OUTK + wn + 8 * t + 2 * (lane & 3);
            float2 v0; v0.x = acc[i][t][0]; v0.y = acc[i][t][1];
            float2 v1; v1.x = acc[i][t][2]; v1.y = acc[i][t][3];
            *reinterpret_cast<float2*>(out + (size_t)r0 * OUTD + cN)       = v0;
            *reinterpret_cast<float2*>(out + (size_t)(r0 + 8) * OUTD + cN) = v1;
        }
    }
}

// ---------------------------------------------------------------------------
extern "C" void kernel_launch(void* const* d_in, const int* in_sizes, int n_in,
                              void* d_out, int out_size)
{
    const float* feats  = (const float*)d_in[0];
    const float* coords = (const float*)d_in[1];
    const float* mrho   = (const float*)d_in[2];
    const float* mtheta = (const float*)d_in[3];
    const float* prho   = (const float*)d_in[4];
    const float* ptheta = (const float*)d_in[5];
    const float* convw  = (const float*)d_in[6];
    float* out = (float*)d_out;

    cudaFuncSetAttribute(k_mma, cudaFuncAttributeMaxDynamicSharedMemorySize,
                         NST * STAGE_B);

    dim3 gp(CHUNKS, NKER);
    k_prep<<<gp, 128>>>(convw);
    k_agg<<<BQ, 256>>>(feats, coords, mrho, mtheta, prho, ptheta);
    dim3 gg(MT, NKER);
    k_mma<<<gg, 256, NST * STAGE_B>>>(out);
}

// round 9
// speedup vs baseline: 1.9980x; 1.0462x over previous
#include <cuda_runtime.h>
#include <cuda_fp16.h>
#include <cstdint>

// ---------------------------------------------------------------------------
// Problem constants
// ---------------------------------------------------------------------------
#define NB    128
#define NQ    36
#define NN    36
#define IND   1024
#define NKER  8
#define OUTK  128
#define OUTD  1024
#define BQ    (NB * NQ)          // 4608
#define MT    36                 // M row-tiles of 128
#define CHUNKS 32                // K chunks of 32 over IND=1024
#define TILE_B 8192              // one tile: 128 rows x 32 fp16 x 2B

#define NPREP 256                // prep blocks fused into agg launch

typedef unsigned long long ull;

// ---------------------------------------------------------------------------
// Device-global scratch. A (agg) and B (conv_w^T) both single fp16
// (independent roundings -> output rel err ~3e-4, threshold 1e-3).
// Tile format: 128 rows x 32 cols fp16, rows of 64B, 16B groups XOR-swizzled
// by ((row>>1)&3) -> conflict-free ldmatrix. Each tile is 8KB contiguous.
// A layout: [kker][mt(36)][chunk(32)] x tile;  B: [kker][chunk(32)] x tile.
// ---------------------------------------------------------------------------
__device__ __align__(128) __half g_a_hi[(size_t)NKER * MT * CHUNKS * (TILE_B / 2)];
__device__ __align__(128) __half g_b_hi[(size_t)NKER * CHUNKS * (TILE_B / 2)];

// ---------------------------------------------------------------------------
// PTX helpers (non-"a" features only: valid on plain sm_103 target)
// ---------------------------------------------------------------------------
__device__ __forceinline__ void fma2(ull& d, ull a, ull b) {
    asm("fma.rn.f32x2 %0, %1, %2, %0;" : "+l"(d) : "l"(a), "l"(b));
}
__device__ __forceinline__ ull pack2(float x) {
    ull r;
    asm("mov.b64 %0, {%1, %1};" : "=l"(r) : "r"(__float_as_uint(x)));
    return r;
}
__device__ __forceinline__ uint32_t smem_u32(const void* p) {
    uint32_t a;
    asm("{ .reg .u64 t; cvta.to.shared.u64 t, %1; cvt.u32.u64 %0, t; }" : "=r"(a) : "l"(p));
    return a;
}
__device__ __forceinline__ void ldx4(uint32_t* r, uint32_t addr) {
    asm volatile("ldmatrix.sync.aligned.m8n8.x4.shared.b16 {%0,%1,%2,%3}, [%4];"
                 : "=r"(r[0]), "=r"(r[1]), "=r"(r[2]), "=r"(r[3]) : "r"(addr));
}
__device__ __forceinline__ void mma16816(float* d, const uint32_t* a, const uint32_t* b) {
    asm volatile(
        "mma.sync.aligned.m16n8k16.row.col.f32.f16.f16.f32 "
        "{%0,%1,%2,%3}, {%4,%5,%6,%7}, {%8,%9}, {%0,%1,%2,%3};"
        : "+f"(d[0]), "+f"(d[1]), "+f"(d[2]), "+f"(d[3])
        : "r"(a[0]), "r"(a[1]), "r"(a[2]), "r"(a[3]), "r"(b[0]), "r"(b[1]));
}
__device__ __forceinline__ void mbar_init(uint32_t addr, uint32_t cnt) {
    asm volatile("mbarrier.init.shared.b64 [%0], %1;" :: "r"(addr), "r"(cnt) : "memory");
}
__device__ __forceinline__ void mbar_expect_tx(uint32_t addr, uint32_t bytes) {
    asm volatile("mbarrier.arrive.expect_tx.shared.b64 _, [%0], %1;"
                 :: "r"(addr), "r"(bytes) : "memory");
}
__device__ __forceinline__ void mbar_wait_acq(uint32_t addr, uint32_t parity) {
    asm volatile(
        "{\n\t.reg .pred P;\n\t"
        "W%=:\n\t"
        "mbarrier.try_wait.parity.acquire.cta.shared::cta.b64 P, [%0], %1;\n\t"
        "@!P bra W%=;\n\t}"
        :: "r"(addr), "r"(parity) : "memory");
}
__device__ __forceinline__ void bulk_g2s(uint32_t dst, const void* src, uint32_t bytes,
                                         uint32_t mbar) {
    asm volatile(
        "cp.async.bulk.shared::cta.global.mbarrier::complete_tx::bytes [%0], [%1], %2, [%3];"
        :: "r"(dst), "l"(src), "r"(bytes), "r"(mbar) : "memory");
}

// ---------------------------------------------------------------------------
// Kernel 1 (fused): [prep 256 | agg 4608] blocks in one launch.
//
// prep role: conv_w (k,d,o) -> B^T tiles [kker][chunk] of 128 n-rows x 32 k.
// agg role:  gaussian weights + weighted aggregation; one block per (b,q),
//            256 threads, thread owns 4 consecutive d-cols for all 8 kernels;
//            emits single fp16 directly in the swizzled GEMM tile layout.
// ---------------------------------------------------------------------------
__global__ void __launch_bounds__(256, 4) k_agg(
    const float* __restrict__ feats, const float* __restrict__ coords,
    const float* __restrict__ mrho,  const float* __restrict__ mtheta,
    const float* __restrict__ prho,  const float* __restrict__ ptheta,
    const float* __restrict__ convw)
{
    __shared__ __align__(16) char smem_buf[16384];
    const int tid = threadIdx.x;

    if (blockIdx.x < NPREP) {
        // ---------------- prep role ----------------
        const int rb = blockIdx.x;
        const int kc = rb & 31;
        const int kk = rb >> 5;

        float* s = reinterpret_cast<float*>(smem_buf);     // 32 x 128 floats
        const float4* src = reinterpret_cast<const float4*>(
            convw + (size_t)kk * (IND * OUTK) + (size_t)kc * (32 * OUTK));
        float4* sd = reinterpret_cast<float4*>(s);
#pragma unroll
        for (int i = 0; i < 4; i++)
            sd[tid + i * 256] = __ldg(&src[tid + i * 256]);
        __syncthreads();

        const size_t tbase = ((size_t)kk * CHUNKS + kc) * TILE_B;
        const int n   = tid & 127;
        const int gg  = (tid >> 7) * 2;        // 2 groups per thread half
        const int swz = (n >> 1) & 3;
#pragma unroll
        for (int gi = 0; gi < 2; gi++) {
            const int g = gg + gi;
            union { __half h[8]; uint4 u; } H;
#pragma unroll
            for (int j = 0; j < 8; j++)
                H.h[j] = __float2half_rn(s[(g * 8 + j) * 128 + n]);
            const uint32_t sw = (uint32_t)(n * 64 + 16 * (g ^ swz));
            *reinterpret_cast<uint4*>((char*)g_b_hi + tbase + sw) = H.u;
        }
        return;
    }

    // ---------------- agg role ----------------
    const int bq = blockIdx.x - NPREP;
    ull* w2s = reinterpret_cast<ull*>(smem_buf);   // [NN][NKER], rows 64B

    if (tid < NN) {
        const float rho = coords[((size_t)bq * NN + tid) * 2 + 0];
        const float th  = coords[((size_t)bq * NN + tid) * 2 + 1];
        float w[NKER];
        float s = 0.0f;
        const float TWO_PI = 6.283185307179586f;
#pragma unroll
        for (int k = 0; k < NKER; k++) {
            const float dr = rho - __ldg(&mrho[k]);
            const float pr = __ldg(&prho[k]);
            const float wr = expf(-0.5f * dr * dr / (1e-14f + pr * pr));
            const float fa = fabsf(th - __ldg(&mtheta[k]));
            const float sa = fabsf(TWO_PI - fa);
            const float an = fminf(fa, sa);
            const float pt = __ldg(&ptheta[k]);
            const float wt = expf(-0.5f * an * an / (1e-14f + pt * pt));
            float wv = wr * wt;
            wv = isnan(wv) ? 0.0f : wv;
            w[k] = wv;
            s += wv;
        }
#pragma unroll
        for (int k = 0; k < NKER; k++)
            w2s[tid * NKER + k] = pack2(w[k] / s);
    }
    __syncthreads();

    ull acc[NKER][2];
#pragma unroll
    for (int k = 0; k < NKER; k++) { acc[k][0] = 0ULL; acc[k][1] = 0ULL; }

    const ulonglong2* p = reinterpret_cast<const ulonglong2*>(feats)
                        + (size_t)bq * (NN * IND / 4) + tid;
    const ulonglong2* wrow = reinterpret_cast<const ulonglong2*>(w2s);

#pragma unroll 6
    for (int n = 0; n < NN; n++) {
        const ulonglong2 f = __ldcs(p);
        p += IND / 4;
        // 4x LDS.128 (weight pairs) instead of 8x LDS.64
#pragma unroll
        for (int kp = 0; kp < 4; kp++) {
            const ulonglong2 wk = wrow[n * 4 + kp];
            fma2(acc[2 * kp + 0][0], f.x, wk.x);
            fma2(acc[2 * kp + 0][1], f.y, wk.x);
            fma2(acc[2 * kp + 1][0], f.x, wk.y);
            fma2(acc[2 * kp + 1][1], f.y, wk.y);
        }
    }

    // store single fp16 into swizzled tile layout (streaming stores)
    const int row   = bq & 127;
    const int mt128 = bq >> 7;
    const int kc    = tid >> 3;          // chunk index 0..31
    const int g     = (tid >> 1) & 3;    // 16B group within 64B row
    const int half_ = tid & 1;           // low/high 8B of group
    const uint32_t sw = (uint32_t)(row * 64 + 16 * (g ^ ((row >> 1) & 3)) + 8 * half_);

#pragma unroll
    for (int k = 0; k < NKER; k++) {
        float x0 = __uint_as_float((uint32_t)acc[k][0]);
        float x1 = __uint_as_float((uint32_t)(acc[k][0] >> 32));
        float x2 = __uint_as_float((uint32_t)acc[k][1]);
        float x3 = __uint_as_float((uint32_t)(acc[k][1] >> 32));

        union { __half h[4]; ull u; } H;
        H.h[0] = __float2half_rn(x0);
        H.h[1] = __float2half_rn(x1);
        H.h[2] = __float2half_rn(x2);
        H.h[3] = __float2half_rn(x3);

        const size_t tile = ((size_t)(k * MT + mt128) * CHUNKS + kc) * TILE_B;
        __stcs(reinterpret_cast<ull*>((char*)g_a_hi + tile + sw), H.u);
    }
}

// ---------------------------------------------------------------------------
// Kernel 2: HMMA GEMM, single fp16 pass. Block 128x128, 8 warps (warp tile
// 64x32), 6-stage pipeline fed by cp.async.bulk + mbarrier.
// grid (36, 8), 96KB dynamic smem -> 2 blocks/SM, one wave.
// ---------------------------------------------------------------------------
#define NST 6
#define STAGE_B 16384   // Ah 8K | Bh 8K

__global__ void __launch_bounds__(256, 2) k_mma(float* __restrict__ out)
{
    extern __shared__ char dsm[];
    __shared__ __align__(8) ull s_mbar[NST];

    const uint32_t sbase = smem_u32(dsm);
    const uint32_t mb    = smem_u32(s_mbar);

    const int tid  = threadIdx.x;
    const int wid  = tid >> 5;
    const int lane = tid & 31;
    const int mt   = blockIdx.x;   // 0..35
    const int kk   = blockIdx.y;   // 0..7

    const int wm = (wid >> 2) * 64;   // warp M offset (0/64)
    const int wn = (wid & 3) * 32;    // warp N offset (0/32/64/96)

    const char* Abh = (const char*)g_a_hi + (size_t)(kk * MT + mt) * CHUNKS * TILE_B;
    const char* Bbh = (const char*)g_b_hi + (size_t)kk * CHUNKS * TILE_B;

    auto issue_chunk = [&](int c, int s) {
        const uint32_t sb = sbase + (uint32_t)s * STAGE_B;
        const uint32_t fb = mb + 8u * (uint32_t)s;
        mbar_expect_tx(fb, STAGE_B);
        bulk_g2s(sb + 0,    Abh + (size_t)c * TILE_B, TILE_B, fb);
        bulk_g2s(sb + 8192, Bbh + (size_t)c * TILE_B, TILE_B, fb);
    };

    if (tid == 0) {
#pragma unroll
        for (int s = 0; s < NST; s++) mbar_init(mb + 8u * s, 1);
    }
    __syncthreads();
    if (tid == 0) {
#pragma unroll
        for (int s = 0; s < NST - 1; s++) issue_chunk(s, s);
    }

    // ldmatrix per-lane address components
    const int j  = lane >> 3;
    const int rr = lane & 7;
    const int a_row  = wm + ((j & 1) << 3) + rr;   // + 16*i
    const int a_gsel = j >> 1;                     // + 2*ss
    const int swzA   = (a_row >> 1) & 3;
    const int b_n    = wn + ((j >> 1) << 3) + rr;  // + 16*p
    const int b_gsel = j & 1;                      // + 2*ss
    const int swzB   = (b_n >> 1) & 3;

    float acc[4][4][4];
#pragma unroll
    for (int i = 0; i < 4; i++)
#pragma unroll
        for (int t = 0; t < 4; t++)
#pragma unroll
            for (int r = 0; r < 4; r++) acc[i][t][r] = 0.0f;

    int ph[NST] = {0, 0, 0, 0, 0, 0};

    for (int c = 0; c < CHUNKS; c++) {
        const int s = c % NST;
        mbar_wait_acq(mb + 8u * s, ph[s]);
        ph[s] ^= 1;

        const uint32_t sb  = sbase + (uint32_t)s * STAGE_B;
        const uint32_t ahb = sb;
        const uint32_t bhb = sb + 8192;

#pragma unroll
        for (int ss = 0; ss < 2; ss++) {
            uint32_t bh[8];
#pragma unroll
            for (int p = 0; p < 2; p++) {
                const uint32_t boff = (uint32_t)((b_n + 16 * p) * 64
                                    + 16 * ((2 * ss + b_gsel) ^ swzB));
                ldx4(&bh[4 * p], bhb + boff);
            }
#pragma unroll
            for (int i = 0; i < 4; i++) {
                uint32_t ah[4];
                const uint32_t aoff = (uint32_t)((a_row + 16 * i) * 64
                                    + 16 * ((2 * ss + a_gsel) ^ swzA));
                ldx4(ah, ahb + aoff);
#pragma unroll
                for (int t = 0; t < 4; t++)
                    mma16816(acc[i][t], ah, &bh[2 * t]);
            }
        }

        __syncthreads();
        if (c + NST - 1 < CHUNKS && tid == 0)
            issue_chunk(c + NST - 1, (c + NST - 1) % NST);
    }

    // epilogue
#pragma unroll
    for (int i = 0; i < 4; i++) {
        const int r0 = mt * 128 + wm + 16 * i + (lane >> 2);
#pragma unroll
        for (int t = 0; t < 4; t++) {
            const int cN = kk * OUTK + wn + 8 * t + 2 * (lane & 3);
            float2 v0; v0.x = acc[i][t][0]; v0.y = acc[i][t][1];
            float2 v1; v1.x = acc[i][t][2]; v1.y = acc[i][t][3];
            *reinterpret_cast<float2*>(out + (size_t)r0 * OUTD + cN)       = v0;
            *reinterpret_cast<float2*>(out + (size_t)(r0 + 8) * OUTD + cN) = v1;
        }
    }
}

// ---------------------------------------------------------------------------
extern "C" void kernel_launch(void* const* d_in, const int* in_sizes, int n_in,
                              void* d_out, int out_size)
{
    const float* feats  = (const float*)d_in[0];
    const float* coords = (const float*)d_in[1];
    const float* mrho   = (const float*)d_in[2];
    const float* mtheta = (const float*)d_in[3];
    const float* prho   = (const float*)d_in[4];
    const float* ptheta = (const float*)d_in[5];
    const float* convw  = (const float*)d_in[6];
    float* out = (float*)d_out;

    cudaFuncSetAttribute(k_mma, cudaFuncAttributeMaxDynamicSharedMemorySize,
                         NST * STAGE_B);

    k_agg<<<NPREP + BQ, 256>>>(feats, coords, mrho, mtheta, prho, ptheta, convw);
    dim3 gg(MT, NKER);
    k_mma<<<gg, 256, NST * STAGE_B>>>(out);
}